// round 16
// baseline (speedup 1.0000x reference)
#include <cuda_runtime.h>
#include <cuda_fp16.h>
#include <cstdint>

#define NN 50000
#define EE 800000
#define HH 4

// -------- scratch (device globals, no allocations) --------
// halves: hfeat NN*256 | bufA NN*256 | bufB NN*256
__device__ __half g_hf[(size_t)NN * 256 * 3];
// floats: W2ext 256*168 | el NN*4 | er NN*4
__device__ float g_pool[256 * 168 + (size_t)NN * 8];
// ints: rowptr NN+1 | deg NN | cursor NN | srcS EE | gmax 4
__device__ int g_ipool[(size_t)NN * 3 + 1 + (size_t)EE + 4];

__device__ __forceinline__ unsigned fkey(float f) {
    unsigned b = __float_as_uint(f);
    return (b & 0x80000000u) ? ~b : (b | 0x80000000u);
}
__device__ __forceinline__ float fdecode(unsigned k) {
    unsigned b = (k & 0x80000000u) ? (k ^ 0x80000000u) : ~k;
    return __uint_as_float(b);
}

// -------- small utility kernels --------
__global__ void zero_int(int* p, int n) {
    int t = blockIdx.x * blockDim.x + threadIdx.x;
    if (t < n) p[t] = 0;
}
__global__ void zero_att(float* p, unsigned* gmax, int n) {
    int t = blockIdx.x * blockDim.x + threadIdx.x;
    if (t < n) p[t] = 0.f;
    if (t < 4) gmax[t] = 0u;
}
__global__ void hist_kernel(const int* __restrict__ dst, int* __restrict__ deg, int E) {
    int t = blockIdx.x * blockDim.x + threadIdx.x;
    if (t < E) atomicAdd(&deg[dst[t]], 1);
}
__global__ void scan_kernel(const int* __restrict__ deg, int* __restrict__ rowptr,
                            int* __restrict__ cursor, int N, int E) {
    __shared__ int sums[1024];
    int t = threadIdx.x;
    int chunk = (N + 1023) >> 10;
    int lo = t * chunk, hi = min(N, lo + chunk);
    int s = 0;
    for (int i = lo; i < hi; i++) s += deg[i];
    sums[t] = s;
    __syncthreads();
    for (int off = 1; off < 1024; off <<= 1) {
        int v = (t >= off) ? sums[t - off] : 0;
        __syncthreads();
        sums[t] += v;
        __syncthreads();
    }
    int run = (t == 0) ? 0 : sums[t - 1];
    for (int i = lo; i < hi; i++) { rowptr[i] = run; cursor[i] = run; run += deg[i]; }
    if (lo < N && hi == N) rowptr[N] = E;
}
__global__ void scatter_kernel(const int* __restrict__ src, const int* __restrict__ dst,
                               int* __restrict__ cursor, int* __restrict__ srcSorted, int E) {
    int t = blockIdx.x * blockDim.x + threadIdx.x;
    if (t >= E) return;
    int d = dst[t];
    int pos = atomicAdd(&cursor[d], 1);
    srcSorted[pos] = src[t];
}

// global per-head max of el
__global__ void gmax_kernel(const float* __restrict__ el, unsigned* __restrict__ gmax, int n4) {
    float mx = -3e38f;
    int stride = gridDim.x * blockDim.x;
    for (int i = blockIdx.x * blockDim.x + threadIdx.x; i < n4; i += stride)
        mx = fmaxf(mx, el[i]);
    int h = threadIdx.x & 3;
#pragma unroll
    for (int o = 4; o < 32; o <<= 1)
        mx = fmaxf(mx, __shfl_xor_sync(0xffffffffu, mx, o));
    __shared__ unsigned sm[4];
    if (threadIdx.x < 4) sm[threadIdx.x] = 0u;
    __syncthreads();
    if ((threadIdx.x & 31) < 4) atomicMax(&sm[h], fkey(mx));
    __syncthreads();
    if (threadIdx.x < 4) atomicMax(&gmax[threadIdx.x], sm[threadIdx.x]);
}

// build W2ext[256][168] = [W2 | W2.al2-folded | W2.ar2-folded]
__global__ void build_w2ext(const float* __restrict__ W2, const float* __restrict__ al2,
                            const float* __restrict__ ar2, float* __restrict__ W2e) {
    int t = blockIdx.x * blockDim.x + threadIdx.x;
    if (t >= 256 * 168) return;
    int k = t / 168, j = t - (t / 168) * 168;
    if (j < 160) { W2e[t] = W2[k * 160 + j]; return; }
    int jj = j - 160;
    int h = jj & 3;
    const float* a = (jj >= 4) ? ar2 : al2;
    float s = 0.f;
#pragma unroll
    for (int c = 0; c < 40; c++) s += W2[k * 160 + h * 40 + c] * a[h * 40 + c];
    W2e[t] = s;
}

// -------- fp16 HMMA GEMM, double-buffered, ldmatrix --------
// 128x128 block tile, 8 warps (2x4), 64x32 warp tile = 4x4 m16n8k16 frags.
// ATT: fused el/er partials via shuffles+atomics (layers 0/1, aligned heads).
// EXT: last 8 columns are folded-attention columns -> write el/er fp32;
//      feat (fp16) written with stride Ncols-8.
__device__ __forceinline__ void ldmA4(unsigned& r0, unsigned& r1, unsigned& r2, unsigned& r3, unsigned a) {
    asm volatile("ldmatrix.sync.aligned.m8n8.x4.shared.b16 {%0,%1,%2,%3}, [%4];"
                 : "=r"(r0), "=r"(r1), "=r"(r2), "=r"(r3) : "r"(a));
}
__device__ __forceinline__ void ldmBT4(unsigned& r0, unsigned& r1, unsigned& r2, unsigned& r3, unsigned a) {
    asm volatile("ldmatrix.sync.aligned.m8n8.x4.trans.shared.b16 {%0,%1,%2,%3}, [%4];"
                 : "=r"(r0), "=r"(r1), "=r"(r2), "=r"(r3) : "r"(a));
}

template <bool ATT, bool EXT, bool AHALF>
__global__ __launch_bounds__(256) void gemm_fp16(const float* __restrict__ Af,
                                                 const __half* __restrict__ Ah,
                                                 const float* __restrict__ B,
                                                 __half* __restrict__ Ch,
                                                 int M, int K, int Ncols,
                                                 const float* __restrict__ al,
                                                 const float* __restrict__ ar,
                                                 float* __restrict__ el,
                                                 float* __restrict__ er) {
    __shared__ __align__(16) unsigned char smc[2][8192];
    unsigned smBase = (unsigned)__cvta_generic_to_shared(&smc[0][0]);
    const int nf = EXT ? (Ncols - 8) : Ncols;   // fp16 feat stride

    int tid = threadIdx.x;
    int warp = tid >> 5, lane = tid & 31;
    int gid = lane >> 2, tig = lane & 3;
    int warp_m = warp >> 2, warp_n = warp & 3;
    int rowBase = blockIdx.y * 128;
    int colBase = blockIdx.x * 128;

    int ar_ = tid >> 1;
    int ak = (tid & 1) * 8;
    int br = tid >> 4;
    int bc = (tid & 15) * 8;

    int gr = rowBase + ar_;
    bool aOk = (gr < M);
    int gc = colBase + bc;
    bool bFull = (gc + 7 < Ncols);

    const float*  aBaseF = Af ? (Af + (size_t)gr * K + ak) : nullptr;
    const __half* aBaseH = Ah ? (Ah + (size_t)gr * K + ak) : nullptr;
    const float*  bBase  = B + (size_t)br * Ncols + gc;

    const int aSts = ((ar_ * 32 + ak * 2) ^ (((ar_ >> 2) & 1) << 4));
    const int bSts = 4096 + ((br * 256 + bc * 2) ^ ((br & 7) << 4));

    int lt = lane >> 3, lr = lane & 7;
    unsigned aOff[4];
#pragma unroll
    for (int mi = 0; mi < 4; mi++) {
        int m = warp_m * 64 + mi * 16 + (lt & 1) * 8 + lr;
        int kk = (lt >> 1) * 8;
        aOff[mi] = (unsigned)((m * 32 + kk * 2) ^ (((m >> 2) & 1) << 4));
    }
    unsigned bOff[2];
#pragma unroll
    for (int bi = 0; bi < 2; bi++) {
        int k = (lt & 1) * 8 + lr;
        int n = warp_n * 32 + bi * 16 + (lt >> 1) * 8;
        bOff[bi] = (unsigned)(4096 + ((k * 256 + n * 2) ^ ((k & 7) << 4)));
    }

    float acc[4][4][4];
#pragma unroll
    for (int i = 0; i < 4; i++)
#pragma unroll
        for (int j = 0; j < 4; j++)
#pragma unroll
            for (int c = 0; c < 4; c++) acc[i][j][c] = 0.f;

    const int P = K >> 4;
    uint4 stA;
    float rb[8];

    auto loadA = [&](int p) {
        if (AHALF) {
            stA = aOk ? *reinterpret_cast<const uint4*>(aBaseH + p * 16)
                      : make_uint4(0, 0, 0, 0);
        } else {
            float la[8];
            if (aOk) {
                float4 a0 = *reinterpret_cast<const float4*>(aBaseF + p * 16);
                float4 a1 = *reinterpret_cast<const float4*>(aBaseF + p * 16 + 4);
                la[0] = a0.x; la[1] = a0.y; la[2] = a0.z; la[3] = a0.w;
                la[4] = a1.x; la[5] = a1.y; la[6] = a1.z; la[7] = a1.w;
            } else {
#pragma unroll
                for (int i = 0; i < 8; i++) la[i] = 0.f;
            }
            __half2 h0 = __floats2half2_rn(la[0], la[1]);
            __half2 h1 = __floats2half2_rn(la[2], la[3]);
            __half2 h2 = __floats2half2_rn(la[4], la[5]);
            __half2 h3 = __floats2half2_rn(la[6], la[7]);
            stA.x = *reinterpret_cast<unsigned*>(&h0);
            stA.y = *reinterpret_cast<unsigned*>(&h1);
            stA.z = *reinterpret_cast<unsigned*>(&h2);
            stA.w = *reinterpret_cast<unsigned*>(&h3);
        }
    };
    auto loadB = [&](int p) {
        const float* bp = bBase + (size_t)p * 16 * Ncols;
        if (bFull) {
            float4 b0 = *reinterpret_cast<const float4*>(bp);
            float4 b1 = *reinterpret_cast<const float4*>(bp + 4);
            rb[0] = b0.x; rb[1] = b0.y; rb[2] = b0.z; rb[3] = b0.w;
            rb[4] = b1.x; rb[5] = b1.y; rb[6] = b1.z; rb[7] = b1.w;
        } else {
#pragma unroll
            for (int j = 0; j < 8; j++)
                rb[j] = (gc + j < Ncols) ? bp[j] : 0.f;
        }
    };
    auto stsPanel = [&](int buf) {
        *reinterpret_cast<uint4*>(&smc[buf][aSts]) = stA;
        __half2 h0 = __floats2half2_rn(rb[0], rb[1]);
        __half2 h1 = __floats2half2_rn(rb[2], rb[3]);
        __half2 h2 = __floats2half2_rn(rb[4], rb[5]);
        __half2 h3 = __floats2half2_rn(rb[6], rb[7]);
        uint4 u;
        u.x = *reinterpret_cast<unsigned*>(&h0);
        u.y = *reinterpret_cast<unsigned*>(&h1);
        u.z = *reinterpret_cast<unsigned*>(&h2);
        u.w = *reinterpret_cast<unsigned*>(&h3);
        *reinterpret_cast<uint4*>(&smc[buf][bSts]) = u;
    };

    loadA(0); loadB(0);
    stsPanel(0);
    __syncthreads();

    for (int p = 0; p < P; p++) {
        int cur = p & 1, nxt = cur ^ 1;
        if (p + 1 < P) { loadA(p + 1); loadB(p + 1); }

        unsigned base = smBase + cur * 8192;
        unsigned af[4][4], bf[2][4];
#pragma unroll
        for (int mi = 0; mi < 4; mi++)
            ldmA4(af[mi][0], af[mi][1], af[mi][2], af[mi][3], base + aOff[mi]);
#pragma unroll
        for (int bi = 0; bi < 2; bi++)
            ldmBT4(bf[bi][0], bf[bi][1], bf[bi][2], bf[bi][3], base + bOff[bi]);

#pragma unroll
        for (int mi = 0; mi < 4; mi++)
#pragma unroll
            for (int ni = 0; ni < 4; ni++) {
                unsigned b0 = bf[ni >> 1][(ni & 1) * 2];
                unsigned b1 = bf[ni >> 1][(ni & 1) * 2 + 1];
                asm volatile(
                    "mma.sync.aligned.m16n8k16.row.col.f32.f16.f16.f32 "
                    "{%0,%1,%2,%3}, {%4,%5,%6,%7}, {%8,%9}, {%0,%1,%2,%3};\n"
                    : "+f"(acc[mi][ni][0]), "+f"(acc[mi][ni][1]),
                      "+f"(acc[mi][ni][2]), "+f"(acc[mi][ni][3])
                    : "r"(af[mi][0]), "r"(af[mi][1]), "r"(af[mi][2]), "r"(af[mi][3]),
                      "r"(b0), "r"(b1));
            }

        if (p + 1 < P) {
            __syncthreads();
            stsPanel(nxt);
            __syncthreads();
        }
    }

    // store outputs
#pragma unroll
    for (int mi = 0; mi < 4; mi++) {
        int r0 = rowBase + warp_m * 64 + mi * 16 + gid;
#pragma unroll
        for (int ni = 0; ni < 4; ni++) {
            int c0 = colBase + warp_n * 32 + ni * 8 + tig * 2;
            if (c0 >= Ncols) continue;
            if (EXT && c0 >= Ncols - 8) {
                int j = c0 - (Ncols - 8);   // even: 0,2,4,6
                if (r0 < M) {
                    float2 v = make_float2(acc[mi][ni][0], acc[mi][ni][1]);
                    if (j < 4) *reinterpret_cast<float2*>(&el[r0 * 4 + j]) = v;
                    else       *reinterpret_cast<float2*>(&er[r0 * 4 + (j - 4)]) = v;
                }
                if (r0 + 8 < M) {
                    float2 v = make_float2(acc[mi][ni][2], acc[mi][ni][3]);
                    if (j < 4) *reinterpret_cast<float2*>(&el[(r0 + 8) * 4 + j]) = v;
                    else       *reinterpret_cast<float2*>(&er[(r0 + 8) * 4 + (j - 4)]) = v;
                }
            } else {
                if (r0 < M)
                    *reinterpret_cast<__half2*>(&Ch[(size_t)r0 * nf + c0]) =
                        __floats2half2_rn(acc[mi][ni][0], acc[mi][ni][1]);
                if (r0 + 8 < M)
                    *reinterpret_cast<__half2*>(&Ch[(size_t)(r0 + 8) * nf + c0]) =
                        __floats2half2_rn(acc[mi][ni][2], acc[mi][ni][3]);
            }
        }
    }

    if (ATT) {
        int h = (colBase + warp_n * 32) >> 6;
#pragma unroll
        for (int mi = 0; mi < 4; mi++) {
            float pl0 = 0.f, pl1 = 0.f, pr0 = 0.f, pr1 = 0.f;
#pragma unroll
            for (int ni = 0; ni < 4; ni++) {
#pragma unroll
                for (int j = 0; j < 2; j++) {
                    int cw = (colBase + warp_n * 32 + ni * 8 + tig * 2 + j) & 63;
                    float av = al[h * 64 + cw];
                    float rv = ar[h * 64 + cw];
                    pl0 += acc[mi][ni][j] * av;
                    pr0 += acc[mi][ni][j] * rv;
                    pl1 += acc[mi][ni][2 + j] * av;
                    pr1 += acc[mi][ni][2 + j] * rv;
                }
            }
#pragma unroll
            for (int o = 1; o <= 2; o <<= 1) {
                pl0 += __shfl_xor_sync(0xffffffffu, pl0, o);
                pr0 += __shfl_xor_sync(0xffffffffu, pr0, o);
                pl1 += __shfl_xor_sync(0xffffffffu, pl1, o);
                pr1 += __shfl_xor_sync(0xffffffffu, pr1, o);
            }
            if (tig == 0) {
                int r0 = rowBase + warp_m * 64 + mi * 16 + gid;
                if (r0 < M) {
                    atomicAdd(&el[r0 * 4 + h], pl0);
                    atomicAdd(&er[r0 * 4 + h], pr0);
                }
                if (r0 + 8 < M) {
                    atomicAdd(&el[(r0 + 8) * 4 + h], pl1);
                    atomicAdd(&er[(r0 + 8) * 4 + h], pr1);
                }
            }
        }
    }
}

// 8 fp16 channels (uint4) fma into fp32 acc
__device__ __forceinline__ void hf8_fma(float* acc, uint4 u, float ee) {
    float2 f;
    f = __half22float2(*reinterpret_cast<__half2*>(&u.x));
    acc[0] += ee * f.x; acc[1] += ee * f.y;
    f = __half22float2(*reinterpret_cast<__half2*>(&u.y));
    acc[2] += ee * f.x; acc[3] += ee * f.y;
    f = __half22float2(*reinterpret_cast<__half2*>(&u.z));
    acc[4] += ee * f.x; acc[5] += ee * f.y;
    f = __half22float2(*reinterpret_cast<__half2*>(&u.w));
    acc[6] += ee * f.x; acc[7] += ee * f.y;
}

// -------- fused softmax + aggregation with cp.async row staging --------
// One warp per dst node; 16-row smem ring per warp; global-max softmax shift.
// MODE 0: D=64, out fp16 [d,256] = elu(acc/den + bias)
// MODE 1: D=40, lanes 0..19, out fp32 logits[d,40] = mean_h(acc/den + bias)
#define AGG_CH 16

template <int D, int MODE>
__global__ __launch_bounds__(256) void gat_aggregate(
    const int* __restrict__ rowptr, const int* __restrict__ srcS,
    const float* __restrict__ el, const float* __restrict__ er,
    const unsigned* __restrict__ gmax,
    const __half* __restrict__ hfeat, const float* __restrict__ bias,
    __half* __restrict__ outH, float* __restrict__ outF, int N) {
    constexpr int HD = 4 * D;
    constexpr int ROWB = HD * 2;                     // 512 or 320 bytes
    extern __shared__ __align__(16) unsigned char dynSm[];
    unsigned char* sRows = dynSm;                    // [8][AGG_CH][ROWB]
    float* sEE = (float*)(dynSm + 8 * AGG_CH * ROWB);      // [8][4][AGG_CH]
    int*   sSrc = (int*)((unsigned char*)sEE + 8 * 4 * AGG_CH * 4); // [8][AGG_CH]
    float* sOut = (float*)((unsigned char*)sSrc + 8 * AGG_CH * 4);  // [8][160] (MODE1)

    int wl = threadIdx.x >> 5, lane = threadIdx.x & 31;
    int d = blockIdx.x * 8 + wl;
    if (d >= N) return;
    int begin = rowptr[d], end = rowptr[d + 1];

    float4 erv = *reinterpret_cast<const float4*>(&er[d * 4]);
    float er4[4] = {erv.x, erv.y, erv.z, erv.w};

    float m[4];
#pragma unroll
    for (int h = 0; h < 4; h++) {
        float v = fdecode(gmax[h]) + er4[h];
        m[h] = v > 0.f ? v : 0.2f * v;
    }

    float acc[8];
#pragma unroll
    for (int j = 0; j < 8; j++) acc[j] = 0.f;
    float den[4] = {0.f, 0.f, 0.f, 0.f};

    const int h = (MODE == 0) ? (lane >> 3) : (lane / 5);
    const bool active = (MODE == 0) ? true : (lane < 20);
    const int cOff = lane * 8;                       // halves (16 B/lane)
    unsigned char* myRows = sRows + (size_t)wl * AGG_CH * ROWB;
    unsigned myRowsA = (unsigned)__cvta_generic_to_shared(myRows);
    float* myEE = sEE + (wl * 4 + h) * AGG_CH;
    int* mySrc = sSrc + wl * AGG_CH;

    for (int base = begin; base < end; base += AGG_CH) {
        int cnt = min(AGG_CH, end - base);
        if (lane < cnt) {
            int s = srcS[base + lane];
            mySrc[lane] = s;
            float4 e4 = *reinterpret_cast<const float4*>(&el[s * 4]);
            float v, ee;
            v = e4.x + er4[0]; v = v > 0.f ? v : 0.2f * v; ee = __expf(v - m[0]); den[0] += ee; sEE[(wl * 4 + 0) * AGG_CH + lane] = ee;
            v = e4.y + er4[1]; v = v > 0.f ? v : 0.2f * v; ee = __expf(v - m[1]); den[1] += ee; sEE[(wl * 4 + 1) * AGG_CH + lane] = ee;
            v = e4.z + er4[2]; v = v > 0.f ? v : 0.2f * v; ee = __expf(v - m[2]); den[2] += ee; sEE[(wl * 4 + 2) * AGG_CH + lane] = ee;
            v = e4.w + er4[3]; v = v > 0.f ? v : 0.2f * v; ee = __expf(v - m[3]); den[3] += ee; sEE[(wl * 4 + 3) * AGG_CH + lane] = ee;
        }
        __syncwarp();

        if (active) {
            for (int t = 0; t < cnt; t++) {
                const __half* g = hfeat + (size_t)mySrc[t] * HD + cOff;
                unsigned dstA = myRowsA + t * ROWB + lane * 16;
                asm volatile("cp.async.cg.shared.global [%0], [%1], 16;"
                             :: "r"(dstA), "l"(g));
            }
        }
        asm volatile("cp.async.commit_group;");
        asm volatile("cp.async.wait_group 0;" ::: "memory");

        if (active) {
            uint4 u = *reinterpret_cast<uint4*>(myRows + lane * 16);
            for (int t = 0; t < cnt - 1; t++) {
                uint4 nu = *reinterpret_cast<uint4*>(myRows + (t + 1) * ROWB + lane * 16);
                hf8_fma(acc, u, myEE[t]);
                u = nu;
            }
            hf8_fma(acc, u, myEE[cnt - 1]);
        }
        __syncwarp();
    }

#pragma unroll
    for (int hh = 0; hh < 4; hh++) {
#pragma unroll
        for (int o = 16; o; o >>= 1)
            den[hh] += __shfl_xor_sync(0xffffffffu, den[hh], o);
        den[hh] = fmaxf(den[hh], 1e-30f);
    }

    if constexpr (MODE == 0) {
        float inv = 1.f / den[h];
        uint4 u;
        unsigned* up = &u.x;
#pragma unroll
        for (int j = 0; j < 4; j++) {
            float v0 = acc[2 * j] * inv + bias[cOff + 2 * j];
            float v1 = acc[2 * j + 1] * inv + bias[cOff + 2 * j + 1];
            v0 = v0 > 0.f ? v0 : expm1f(v0);
            v1 = v1 > 0.f ? v1 : expm1f(v1);
            __half2 hh2 = __floats2half2_rn(v0, v1);
            up[j] = *reinterpret_cast<unsigned*>(&hh2);
        }
        *reinterpret_cast<uint4*>(outH + (size_t)d * 256 + cOff) = u;
    } else {
        if (active) {
            float inv = 1.f / den[h];
#pragma unroll
            for (int j = 0; j < 8; j++)
                sOut[wl * 160 + cOff + j] = acc[j] * inv + bias[cOff + j];
        }
        __syncwarp();
        float* lg = outF + (size_t)d * 40;
        const float* so = sOut + wl * 160;
        {
            int c = lane;
            lg[c] = 0.25f * (so[c] + so[40 + c] + so[80 + c] + so[120 + c]);
        }
        if (lane < 8) {
            int c = 32 + lane;
            lg[c] = 0.25f * (so[c] + so[40 + c] + so[80 + c] + so[120 + c]);
        }
    }
}

// ---------------------------------------------------------------
extern "C" void kernel_launch(void* const* d_in, const int* in_sizes, int n_in,
                              void* d_out, int out_size) {
    const float* x  = (const float*)d_in[0];
    const int*   ei = (const int*)d_in[1];
    const float* W0  = (const float*)d_in[2];
    const float* al0 = (const float*)d_in[3];
    const float* ar0 = (const float*)d_in[4];
    const float* b0  = (const float*)d_in[5];
    const float* W1  = (const float*)d_in[6];
    const float* al1 = (const float*)d_in[7];
    const float* ar1 = (const float*)d_in[8];
    const float* b1  = (const float*)d_in[9];
    const float* W2  = (const float*)d_in[10];
    const float* al2 = (const float*)d_in[11];
    const float* ar2 = (const float*)d_in[12];
    const float* b2  = (const float*)d_in[13];

    int E = in_sizes[1] / 2;
    int N = in_sizes[0] / 256;
    const int* src = ei;
    const int* dst = ei + E;

    void* hv = nullptr;
    cudaGetSymbolAddress(&hv, g_hf);
    __half* hfeat = (__half*)hv;
    __half* bufA  = hfeat + (size_t)NN * 256;
    __half* bufB  = bufA + (size_t)NN * 256;

    void* pv = nullptr;
    cudaGetSymbolAddress(&pv, g_pool);
    float* W2e = (float*)pv;
    float* el  = W2e + 256 * 168;
    float* er  = el + (size_t)NN * 4;

    void* iv = nullptr;
    cudaGetSymbolAddress(&iv, g_ipool);
    int* rowptr = (int*)iv;
    int* deg    = rowptr + NN + 1;
    int* cursor = deg + NN;
    int* srcS   = cursor + NN;
    unsigned* gmax = (unsigned*)(srcS + EE);

    const int TB = 256;
    auto blocks = [](long n, int tb) { return (int)((n + tb - 1) / tb); };

    // dynamic smem sizes for aggregates
    const int smem0 = 8 * AGG_CH * 512 + 8 * 4 * AGG_CH * 4 + 8 * AGG_CH * 4 + 8 * 160 * 4;
    const int smem1 = 8 * AGG_CH * 320 + 8 * 4 * AGG_CH * 4 + 8 * AGG_CH * 4 + 8 * 160 * 4;
    static bool attrSet = false;
    if (!attrSet) {
        cudaFuncSetAttribute(gat_aggregate<64, 0>, cudaFuncAttributeMaxDynamicSharedMemorySize, smem0);
        cudaFuncSetAttribute(gat_aggregate<40, 1>, cudaFuncAttributeMaxDynamicSharedMemorySize, smem1);
        attrSet = true;
    }

    // ---- build CSR (by dst) ----
    zero_int<<<blocks(N, TB), TB>>>(deg, N);
    hist_kernel<<<blocks(E, TB), TB>>>(dst, deg, E);
    scan_kernel<<<1, 1024>>>(deg, rowptr, cursor, N, E);
    scatter_kernel<<<blocks(E, TB), TB>>>(src, dst, cursor, srcS, E);

    int aggBlocks = (N + 7) / 8;
    int gy = (N + 127) / 128;

    // ---- layer 0: x (fp32) -> bufA (fp16) ----
    zero_att<<<blocks((long)N * 8, TB), TB>>>(el, gmax, N * 8);
    gemm_fp16<true, false, false><<<dim3(2, gy), 256>>>(x, nullptr, W0, hfeat,
                                                        N, 256, 256, al0, ar0, el, er);
    gmax_kernel<<<128, 256>>>(el, gmax, N * 4);
    gat_aggregate<64, 0><<<aggBlocks, 256, smem0>>>(rowptr, srcS, el, er, gmax, hfeat, b0, bufA, nullptr, N);

    // ---- layer 1: bufA (fp16) -> bufB (fp16) ----
    zero_att<<<blocks((long)N * 8, TB), TB>>>(el, gmax, N * 8);
    gemm_fp16<true, false, true><<<dim3(2, gy), 256>>>(nullptr, bufA, W1, hfeat,
                                                       N, 256, 256, al1, ar1, el, er);
    gmax_kernel<<<128, 256>>>(el, gmax, N * 4);
    gat_aggregate<64, 0><<<aggBlocks, 256, smem0>>>(rowptr, srcS, el, er, gmax, hfeat, b1, bufB, nullptr, N);

    // ---- layer 2: bufB (fp16) -> logits; el/er via appended columns ----
    build_w2ext<<<blocks(256 * 168, TB), TB>>>(W2, al2, ar2, W2e);
    gemm_fp16<false, true, true><<<dim3(2, gy), 256>>>(nullptr, bufB, W2e, hfeat,
                                                       N, 256, 168, nullptr, nullptr, el, er);
    zero_int<<<1, 32>>>((int*)gmax, 4);
    gmax_kernel<<<128, 256>>>(el, gmax, N * 4);
    gat_aggregate<40, 1><<<aggBlocks, 256, smem1>>>(rowptr, srcS, el, er, gmax, hfeat, b2, nullptr, (float*)d_out, N);
}

// round 17
// speedup vs baseline: 1.1284x; 1.1284x over previous
#include <cuda_runtime.h>
#include <cuda_fp16.h>
#include <cstdint>

#define NN 50000
#define EE 800000
#define HH 4

// -------- scratch (device globals, no allocations) --------
// halves: hfeat NN*256 | bufA NN*256 | bufB NN*256
__device__ __half g_hf[(size_t)NN * 256 * 3];
// floats: W2ext 256*168 | el NN*4 | er NN*4
__device__ float g_pool[256 * 168 + (size_t)NN * 8];
// ints: rowptr NN+1 | deg NN | cursor NN | srcS EE | gmax 4
__device__ int g_ipool[(size_t)NN * 3 + 1 + (size_t)EE + 4];

__device__ __forceinline__ unsigned fkey(float f) {
    unsigned b = __float_as_uint(f);
    return (b & 0x80000000u) ? ~b : (b | 0x80000000u);
}
__device__ __forceinline__ float fdecode(unsigned k) {
    unsigned b = (k & 0x80000000u) ? (k ^ 0x80000000u) : ~k;
    return __uint_as_float(b);
}

// -------- small utility kernels --------
__global__ void zero_int(int* p, int n) {
    int t = blockIdx.x * blockDim.x + threadIdx.x;
    if (t < n) p[t] = 0;
}
__global__ void zero_att(float* p, unsigned* gmax, int n) {
    int t = blockIdx.x * blockDim.x + threadIdx.x;
    if (t < n) p[t] = 0.f;
    if (t < 4) gmax[t] = 0u;
}
__global__ void hist_kernel(const int* __restrict__ dst, int* __restrict__ deg, int E) {
    int t = blockIdx.x * blockDim.x + threadIdx.x;
    if (t < E) atomicAdd(&deg[dst[t]], 1);
}
__global__ void scan_kernel(const int* __restrict__ deg, int* __restrict__ rowptr,
                            int* __restrict__ cursor, int N, int E) {
    __shared__ int sums[1024];
    int t = threadIdx.x;
    int chunk = (N + 1023) >> 10;
    int lo = t * chunk, hi = min(N, lo + chunk);
    int s = 0;
    for (int i = lo; i < hi; i++) s += deg[i];
    sums[t] = s;
    __syncthreads();
    for (int off = 1; off < 1024; off <<= 1) {
        int v = (t >= off) ? sums[t - off] : 0;
        __syncthreads();
        sums[t] += v;
        __syncthreads();
    }
    int run = (t == 0) ? 0 : sums[t - 1];
    for (int i = lo; i < hi; i++) { rowptr[i] = run; cursor[i] = run; run += deg[i]; }
    if (lo < N && hi == N) rowptr[N] = E;
}
__global__ void scatter_kernel(const int* __restrict__ src, const int* __restrict__ dst,
                               int* __restrict__ cursor, int* __restrict__ srcSorted, int E) {
    int t = blockIdx.x * blockDim.x + threadIdx.x;
    if (t >= E) return;
    int d = dst[t];
    int pos = atomicAdd(&cursor[d], 1);
    srcSorted[pos] = src[t];
}

// global per-head max of el
__global__ void gmax_kernel(const float* __restrict__ el, unsigned* __restrict__ gmax, int n4) {
    float mx = -3e38f;
    int stride = gridDim.x * blockDim.x;
    for (int i = blockIdx.x * blockDim.x + threadIdx.x; i < n4; i += stride)
        mx = fmaxf(mx, el[i]);
    int h = threadIdx.x & 3;
#pragma unroll
    for (int o = 4; o < 32; o <<= 1)
        mx = fmaxf(mx, __shfl_xor_sync(0xffffffffu, mx, o));
    __shared__ unsigned sm[4];
    if (threadIdx.x < 4) sm[threadIdx.x] = 0u;
    __syncthreads();
    if ((threadIdx.x & 31) < 4) atomicMax(&sm[h], fkey(mx));
    __syncthreads();
    if (threadIdx.x < 4) atomicMax(&gmax[threadIdx.x], sm[threadIdx.x]);
}

// build W2ext[256][168] = [W2 | W2.al2-folded | W2.ar2-folded]
__global__ void build_w2ext(const float* __restrict__ W2, const float* __restrict__ al2,
                            const float* __restrict__ ar2, float* __restrict__ W2e) {
    int t = blockIdx.x * blockDim.x + threadIdx.x;
    if (t >= 256 * 168) return;
    int k = t / 168, j = t - (t / 168) * 168;
    if (j < 160) { W2e[t] = W2[k * 160 + j]; return; }
    int jj = j - 160;
    int h = jj & 3;
    const float* a = (jj >= 4) ? ar2 : al2;
    float s = 0.f;
#pragma unroll
    for (int c = 0; c < 40; c++) s += W2[k * 160 + h * 40 + c] * a[h * 40 + c];
    W2e[t] = s;
}

// -------- fp16 HMMA GEMM, double-buffered, ldmatrix --------
// 128x128 block tile, 8 warps (2x4), 64x32 warp tile = 4x4 m16n8k16 frags.
// ATT: fused el/er partials via shuffles+atomics (layers 0/1, aligned heads).
// EXT: last 8 columns are folded-attention columns -> write el/er fp32;
//      feat (fp16) written with stride Ncols-8.
__device__ __forceinline__ void ldmA4(unsigned& r0, unsigned& r1, unsigned& r2, unsigned& r3, unsigned a) {
    asm volatile("ldmatrix.sync.aligned.m8n8.x4.shared.b16 {%0,%1,%2,%3}, [%4];"
                 : "=r"(r0), "=r"(r1), "=r"(r2), "=r"(r3) : "r"(a));
}
__device__ __forceinline__ void ldmBT4(unsigned& r0, unsigned& r1, unsigned& r2, unsigned& r3, unsigned a) {
    asm volatile("ldmatrix.sync.aligned.m8n8.x4.trans.shared.b16 {%0,%1,%2,%3}, [%4];"
                 : "=r"(r0), "=r"(r1), "=r"(r2), "=r"(r3) : "r"(a));
}

template <bool ATT, bool EXT, bool AHALF>
__global__ __launch_bounds__(256) void gemm_fp16(const float* __restrict__ Af,
                                                 const __half* __restrict__ Ah,
                                                 const float* __restrict__ B,
                                                 __half* __restrict__ Ch,
                                                 int M, int K, int Ncols,
                                                 const float* __restrict__ al,
                                                 const float* __restrict__ ar,
                                                 float* __restrict__ el,
                                                 float* __restrict__ er) {
    __shared__ __align__(16) unsigned char smc[2][8192];
    unsigned smBase = (unsigned)__cvta_generic_to_shared(&smc[0][0]);
    const int nf = EXT ? (Ncols - 8) : Ncols;   // fp16 feat stride

    int tid = threadIdx.x;
    int warp = tid >> 5, lane = tid & 31;
    int gid = lane >> 2, tig = lane & 3;
    int warp_m = warp >> 2, warp_n = warp & 3;
    int rowBase = blockIdx.y * 128;
    int colBase = blockIdx.x * 128;

    int ar_ = tid >> 1;
    int ak = (tid & 1) * 8;
    int br = tid >> 4;
    int bc = (tid & 15) * 8;

    int gr = rowBase + ar_;
    bool aOk = (gr < M);
    int gc = colBase + bc;
    bool bFull = (gc + 7 < Ncols);

    const float*  aBaseF = Af ? (Af + (size_t)gr * K + ak) : nullptr;
    const __half* aBaseH = Ah ? (Ah + (size_t)gr * K + ak) : nullptr;
    const float*  bBase  = B + (size_t)br * Ncols + gc;

    const int aSts = ((ar_ * 32 + ak * 2) ^ (((ar_ >> 2) & 1) << 4));
    const int bSts = 4096 + ((br * 256 + bc * 2) ^ ((br & 7) << 4));

    int lt = lane >> 3, lr = lane & 7;
    unsigned aOff[4];
#pragma unroll
    for (int mi = 0; mi < 4; mi++) {
        int m = warp_m * 64 + mi * 16 + (lt & 1) * 8 + lr;
        int kk = (lt >> 1) * 8;
        aOff[mi] = (unsigned)((m * 32 + kk * 2) ^ (((m >> 2) & 1) << 4));
    }
    unsigned bOff[2];
#pragma unroll
    for (int bi = 0; bi < 2; bi++) {
        int k = (lt & 1) * 8 + lr;
        int n = warp_n * 32 + bi * 16 + (lt >> 1) * 8;
        bOff[bi] = (unsigned)(4096 + ((k * 256 + n * 2) ^ ((k & 7) << 4)));
    }

    float acc[4][4][4];
#pragma unroll
    for (int i = 0; i < 4; i++)
#pragma unroll
        for (int j = 0; j < 4; j++)
#pragma unroll
            for (int c = 0; c < 4; c++) acc[i][j][c] = 0.f;

    const int P = K >> 4;
    uint4 stA;
    float rb[8];

    auto loadA = [&](int p) {
        if (AHALF) {
            stA = aOk ? *reinterpret_cast<const uint4*>(aBaseH + p * 16)
                      : make_uint4(0, 0, 0, 0);
        } else {
            float la[8];
            if (aOk) {
                float4 a0 = *reinterpret_cast<const float4*>(aBaseF + p * 16);
                float4 a1 = *reinterpret_cast<const float4*>(aBaseF + p * 16 + 4);
                la[0] = a0.x; la[1] = a0.y; la[2] = a0.z; la[3] = a0.w;
                la[4] = a1.x; la[5] = a1.y; la[6] = a1.z; la[7] = a1.w;
            } else {
#pragma unroll
                for (int i = 0; i < 8; i++) la[i] = 0.f;
            }
            __half2 h0 = __floats2half2_rn(la[0], la[1]);
            __half2 h1 = __floats2half2_rn(la[2], la[3]);
            __half2 h2 = __floats2half2_rn(la[4], la[5]);
            __half2 h3 = __floats2half2_rn(la[6], la[7]);
            stA.x = *reinterpret_cast<unsigned*>(&h0);
            stA.y = *reinterpret_cast<unsigned*>(&h1);
            stA.z = *reinterpret_cast<unsigned*>(&h2);
            stA.w = *reinterpret_cast<unsigned*>(&h3);
        }
    };
    auto loadB = [&](int p) {
        const float* bp = bBase + (size_t)p * 16 * Ncols;
        if (bFull) {
            float4 b0 = *reinterpret_cast<const float4*>(bp);
            float4 b1 = *reinterpret_cast<const float4*>(bp + 4);
            rb[0] = b0.x; rb[1] = b0.y; rb[2] = b0.z; rb[3] = b0.w;
            rb[4] = b1.x; rb[5] = b1.y; rb[6] = b1.z; rb[7] = b1.w;
        } else {
#pragma unroll
            for (int j = 0; j < 8; j++)
                rb[j] = (gc + j < Ncols) ? bp[j] : 0.f;
        }
    };
    auto stsPanel = [&](int buf) {
        *reinterpret_cast<uint4*>(&smc[buf][aSts]) = stA;
        __half2 h0 = __floats2half2_rn(rb[0], rb[1]);
        __half2 h1 = __floats2half2_rn(rb[2], rb[3]);
        __half2 h2 = __floats2half2_rn(rb[4], rb[5]);
        __half2 h3 = __floats2half2_rn(rb[6], rb[7]);
        uint4 u;
        u.x = *reinterpret_cast<unsigned*>(&h0);
        u.y = *reinterpret_cast<unsigned*>(&h1);
        u.z = *reinterpret_cast<unsigned*>(&h2);
        u.w = *reinterpret_cast<unsigned*>(&h3);
        *reinterpret_cast<uint4*>(&smc[buf][bSts]) = u;
    };

    loadA(0); loadB(0);
    stsPanel(0);
    __syncthreads();

    for (int p = 0; p < P; p++) {
        int cur = p & 1, nxt = cur ^ 1;
        if (p + 1 < P) { loadA(p + 1); loadB(p + 1); }

        unsigned base = smBase + cur * 8192;
        unsigned af[4][4], bf[2][4];
#pragma unroll
        for (int mi = 0; mi < 4; mi++)
            ldmA4(af[mi][0], af[mi][1], af[mi][2], af[mi][3], base + aOff[mi]);
#pragma unroll
        for (int bi = 0; bi < 2; bi++)
            ldmBT4(bf[bi][0], bf[bi][1], bf[bi][2], bf[bi][3], base + bOff[bi]);

#pragma unroll
        for (int mi = 0; mi < 4; mi++)
#pragma unroll
            for (int ni = 0; ni < 4; ni++) {
                unsigned b0 = bf[ni >> 1][(ni & 1) * 2];
                unsigned b1 = bf[ni >> 1][(ni & 1) * 2 + 1];
                asm volatile(
                    "mma.sync.aligned.m16n8k16.row.col.f32.f16.f16.f32 "
                    "{%0,%1,%2,%3}, {%4,%5,%6,%7}, {%8,%9}, {%0,%1,%2,%3};\n"
                    : "+f"(acc[mi][ni][0]), "+f"(acc[mi][ni][1]),
                      "+f"(acc[mi][ni][2]), "+f"(acc[mi][ni][3])
                    : "r"(af[mi][0]), "r"(af[mi][1]), "r"(af[mi][2]), "r"(af[mi][3]),
                      "r"(b0), "r"(b1));
            }

        if (p + 1 < P) {
            __syncthreads();
            stsPanel(nxt);
            __syncthreads();
        }
    }

    // store outputs
#pragma unroll
    for (int mi = 0; mi < 4; mi++) {
        int r0 = rowBase + warp_m * 64 + mi * 16 + gid;
#pragma unroll
        for (int ni = 0; ni < 4; ni++) {
            int c0 = colBase + warp_n * 32 + ni * 8 + tig * 2;
            if (c0 >= Ncols) continue;
            if (EXT && c0 >= Ncols - 8) {
                int j = c0 - (Ncols - 8);   // even: 0,2,4,6
                if (r0 < M) {
                    float2 v = make_float2(acc[mi][ni][0], acc[mi][ni][1]);
                    if (j < 4) *reinterpret_cast<float2*>(&el[r0 * 4 + j]) = v;
                    else       *reinterpret_cast<float2*>(&er[r0 * 4 + (j - 4)]) = v;
                }
                if (r0 + 8 < M) {
                    float2 v = make_float2(acc[mi][ni][2], acc[mi][ni][3]);
                    if (j < 4) *reinterpret_cast<float2*>(&el[(r0 + 8) * 4 + j]) = v;
                    else       *reinterpret_cast<float2*>(&er[(r0 + 8) * 4 + (j - 4)]) = v;
                }
            } else {
                if (r0 < M)
                    *reinterpret_cast<__half2*>(&Ch[(size_t)r0 * nf + c0]) =
                        __floats2half2_rn(acc[mi][ni][0], acc[mi][ni][1]);
                if (r0 + 8 < M)
                    *reinterpret_cast<__half2*>(&Ch[(size_t)(r0 + 8) * nf + c0]) =
                        __floats2half2_rn(acc[mi][ni][2], acc[mi][ni][3]);
            }
        }
    }

    if (ATT) {
        int h = (colBase + warp_n * 32) >> 6;
#pragma unroll
        for (int mi = 0; mi < 4; mi++) {
            float pl0 = 0.f, pl1 = 0.f, pr0 = 0.f, pr1 = 0.f;
#pragma unroll
            for (int ni = 0; ni < 4; ni++) {
#pragma unroll
                for (int j = 0; j < 2; j++) {
                    int cw = (colBase + warp_n * 32 + ni * 8 + tig * 2 + j) & 63;
                    float av = al[h * 64 + cw];
                    float rv = ar[h * 64 + cw];
                    pl0 += acc[mi][ni][j] * av;
                    pr0 += acc[mi][ni][j] * rv;
                    pl1 += acc[mi][ni][2 + j] * av;
                    pr1 += acc[mi][ni][2 + j] * rv;
                }
            }
#pragma unroll
            for (int o = 1; o <= 2; o <<= 1) {
                pl0 += __shfl_xor_sync(0xffffffffu, pl0, o);
                pr0 += __shfl_xor_sync(0xffffffffu, pr0, o);
                pl1 += __shfl_xor_sync(0xffffffffu, pl1, o);
                pr1 += __shfl_xor_sync(0xffffffffu, pr1, o);
            }
            if (tig == 0) {
                int r0 = rowBase + warp_m * 64 + mi * 16 + gid;
                if (r0 < M) {
                    atomicAdd(&el[r0 * 4 + h], pl0);
                    atomicAdd(&er[r0 * 4 + h], pr0);
                }
                if (r0 + 8 < M) {
                    atomicAdd(&el[(r0 + 8) * 4 + h], pl1);
                    atomicAdd(&er[(r0 + 8) * 4 + h], pr1);
                }
            }
        }
    }
}

// 8 fp16 channels (uint4) fma into fp32 acc
__device__ __forceinline__ void hf8_fma(float* acc, uint4 u, float ee) {
    float2 f;
    f = __half22float2(*reinterpret_cast<__half2*>(&u.x));
    acc[0] += ee * f.x; acc[1] += ee * f.y;
    f = __half22float2(*reinterpret_cast<__half2*>(&u.y));
    acc[2] += ee * f.x; acc[3] += ee * f.y;
    f = __half22float2(*reinterpret_cast<__half2*>(&u.z));
    acc[4] += ee * f.x; acc[5] += ee * f.y;
    f = __half22float2(*reinterpret_cast<__half2*>(&u.w));
    acc[6] += ee * f.x; acc[7] += ee * f.y;
}

// -------- fused softmax + aggregation: one warp per dst node --------
// Direct LDG.128 gathers (8-deep unroll), global-max softmax shift.
// MODE 0: D=64, out fp16 [d,256] = elu(acc/den + bias)
// MODE 1: D=40, lanes 0..19, out fp32 logits[d,40] = mean_h(acc/den + bias)
template <int D, int MODE>
__global__ __launch_bounds__(256) void gat_aggregate(
    const int* __restrict__ rowptr, const int* __restrict__ srcS,
    const float* __restrict__ el, const float* __restrict__ er,
    const unsigned* __restrict__ gmax,
    const __half* __restrict__ hfeat, const float* __restrict__ bias,
    __half* __restrict__ outH, float* __restrict__ outF, int N) {
    constexpr int HD = 4 * D;
    __shared__ float sEE[8][4][32];
    __shared__ int sSrc[8][32];
    __shared__ float sOut[MODE == 1 ? 8 : 1][MODE == 1 ? 160 : 1];
    int wl = threadIdx.x >> 5, lane = threadIdx.x & 31;
    int d = blockIdx.x * 8 + wl;
    if (d >= N) return;
    int begin = rowptr[d], end = rowptr[d + 1];

    float4 erv = *reinterpret_cast<const float4*>(&er[d * 4]);
    float er4[4] = {erv.x, erv.y, erv.z, erv.w};

    // softmax shift from global per-head el max (upper bound of per-node max)
    float m[4];
#pragma unroll
    for (int h = 0; h < 4; h++) {
        float v = fdecode(gmax[h]) + er4[h];
        m[h] = v > 0.f ? v : 0.2f * v;
    }

    float acc[8];
#pragma unroll
    for (int j = 0; j < 8; j++) acc[j] = 0.f;
    float den[4] = {0.f, 0.f, 0.f, 0.f};

    const int h = (MODE == 0) ? (lane >> 3) : (lane / 5);
    const bool active = (MODE == 0) ? true : (lane < 20);
    const int cOff = lane * 8;

    for (int base = begin; base < end; base += 32) {
        int cnt = min(32, end - base);
        if (lane < cnt) {
            int s = srcS[base + lane];
            sSrc[wl][lane] = s;
            float4 e4 = *reinterpret_cast<const float4*>(&el[s * 4]);
            float v, ee;
            v = e4.x + er4[0]; v = v > 0.f ? v : 0.2f * v; ee = __expf(v - m[0]); den[0] += ee; sEE[wl][0][lane] = ee;
            v = e4.y + er4[1]; v = v > 0.f ? v : 0.2f * v; ee = __expf(v - m[1]); den[1] += ee; sEE[wl][1][lane] = ee;
            v = e4.z + er4[2]; v = v > 0.f ? v : 0.2f * v; ee = __expf(v - m[2]); den[2] += ee; sEE[wl][2][lane] = ee;
            v = e4.w + er4[3]; v = v > 0.f ? v : 0.2f * v; ee = __expf(v - m[3]); den[3] += ee; sEE[wl][3][lane] = ee;
        }
        __syncwarp();

        if (active) {
            int t = 0;
            for (; t + 7 < cnt; t += 8) {
                uint4 u0 = *reinterpret_cast<const uint4*>(hfeat + (size_t)sSrc[wl][t + 0] * HD + cOff);
                uint4 u1 = *reinterpret_cast<const uint4*>(hfeat + (size_t)sSrc[wl][t + 1] * HD + cOff);
                uint4 u2 = *reinterpret_cast<const uint4*>(hfeat + (size_t)sSrc[wl][t + 2] * HD + cOff);
                uint4 u3 = *reinterpret_cast<const uint4*>(hfeat + (size_t)sSrc[wl][t + 3] * HD + cOff);
                uint4 u4 = *reinterpret_cast<const uint4*>(hfeat + (size_t)sSrc[wl][t + 4] * HD + cOff);
                uint4 u5 = *reinterpret_cast<const uint4*>(hfeat + (size_t)sSrc[wl][t + 5] * HD + cOff);
                uint4 u6 = *reinterpret_cast<const uint4*>(hfeat + (size_t)sSrc[wl][t + 6] * HD + cOff);
                uint4 u7 = *reinterpret_cast<const uint4*>(hfeat + (size_t)sSrc[wl][t + 7] * HD + cOff);
                hf8_fma(acc, u0, sEE[wl][h][t + 0]);
                hf8_fma(acc, u1, sEE[wl][h][t + 1]);
                hf8_fma(acc, u2, sEE[wl][h][t + 2]);
                hf8_fma(acc, u3, sEE[wl][h][t + 3]);
                hf8_fma(acc, u4, sEE[wl][h][t + 4]);
                hf8_fma(acc, u5, sEE[wl][h][t + 5]);
                hf8_fma(acc, u6, sEE[wl][h][t + 6]);
                hf8_fma(acc, u7, sEE[wl][h][t + 7]);
            }
            for (; t + 1 < cnt; t += 2) {
                uint4 u0 = *reinterpret_cast<const uint4*>(hfeat + (size_t)sSrc[wl][t + 0] * HD + cOff);
                uint4 u1 = *reinterpret_cast<const uint4*>(hfeat + (size_t)sSrc[wl][t + 1] * HD + cOff);
                hf8_fma(acc, u0, sEE[wl][h][t + 0]);
                hf8_fma(acc, u1, sEE[wl][h][t + 1]);
            }
            if (t < cnt) {
                uint4 u0 = *reinterpret_cast<const uint4*>(hfeat + (size_t)sSrc[wl][t] * HD + cOff);
                hf8_fma(acc, u0, sEE[wl][h][t]);
            }
        }
        __syncwarp();
    }

#pragma unroll
    for (int hh = 0; hh < 4; hh++) {
#pragma unroll
        for (int o = 16; o; o >>= 1)
            den[hh] += __shfl_xor_sync(0xffffffffu, den[hh], o);
        den[hh] = fmaxf(den[hh], 1e-30f);
    }

    if constexpr (MODE == 0) {
        float inv = 1.f / den[h];
        uint4 u;
        unsigned* up = &u.x;
#pragma unroll
        for (int j = 0; j < 4; j++) {
            float v0 = acc[2 * j] * inv + bias[cOff + 2 * j];
            float v1 = acc[2 * j + 1] * inv + bias[cOff + 2 * j + 1];
            v0 = v0 > 0.f ? v0 : expm1f(v0);
            v1 = v1 > 0.f ? v1 : expm1f(v1);
            __half2 hh2 = __floats2half2_rn(v0, v1);
            up[j] = *reinterpret_cast<unsigned*>(&hh2);
        }
        *reinterpret_cast<uint4*>(outH + (size_t)d * 256 + cOff) = u;
    } else {
        if (active) {
            float inv = 1.f / den[h];
#pragma unroll
            for (int j = 0; j < 8; j++)
                sOut[wl][cOff + j] = acc[j] * inv + bias[cOff + j];
        }
        __syncwarp();
        float* lg = outF + (size_t)d * 40;
        {
            int c = lane;
            lg[c] = 0.25f * (sOut[wl][c] + sOut[wl][40 + c] + sOut[wl][80 + c] + sOut[wl][120 + c]);
        }
        if (lane < 8) {
            int c = 32 + lane;
            lg[c] = 0.25f * (sOut[wl][c] + sOut[wl][40 + c] + sOut[wl][80 + c] + sOut[wl][120 + c]);
        }
    }
}

// ---------------------------------------------------------------
extern "C" void kernel_launch(void* const* d_in, const int* in_sizes, int n_in,
                              void* d_out, int out_size) {
    const float* x  = (const float*)d_in[0];
    const int*   ei = (const int*)d_in[1];
    const float* W0  = (const float*)d_in[2];
    const float* al0 = (const float*)d_in[3];
    const float* ar0 = (const float*)d_in[4];
    const float* b0  = (const float*)d_in[5];
    const float* W1  = (const float*)d_in[6];
    const float* al1 = (const float*)d_in[7];
    const float* ar1 = (const float*)d_in[8];
    const float* b1  = (const float*)d_in[9];
    const float* W2  = (const float*)d_in[10];
    const float* al2 = (const float*)d_in[11];
    const float* ar2 = (const float*)d_in[12];
    const float* b2  = (const float*)d_in[13];

    int E = in_sizes[1] / 2;
    int N = in_sizes[0] / 256;
    const int* src = ei;
    const int* dst = ei + E;

    void* hv = nullptr;
    cudaGetSymbolAddress(&hv, g_hf);
    __half* hfeat = (__half*)hv;
    __half* bufA  = hfeat + (size_t)NN * 256;
    __half* bufB  = bufA + (size_t)NN * 256;

    void* pv = nullptr;
    cudaGetSymbolAddress(&pv, g_pool);
    float* W2e = (float*)pv;
    float* el  = W2e + 256 * 168;
    float* er  = el + (size_t)NN * 4;

    void* iv = nullptr;
    cudaGetSymbolAddress(&iv, g_ipool);
    int* rowptr = (int*)iv;
    int* deg    = rowptr + NN + 1;
    int* cursor = deg + NN;
    int* srcS   = cursor + NN;
    unsigned* gmax = (unsigned*)(srcS + EE);

    const int TB = 256;
    auto blocks = [](long n, int tb) { return (int)((n + tb - 1) / tb); };

    // ---- build CSR (by dst) ----
    zero_int<<<blocks(N, TB), TB>>>(deg, N);
    hist_kernel<<<blocks(E, TB), TB>>>(dst, deg, E);
    scan_kernel<<<1, 1024>>>(deg, rowptr, cursor, N, E);
    scatter_kernel<<<blocks(E, TB), TB>>>(src, dst, cursor, srcS, E);

    int aggBlocks = (N + 7) / 8;
    int gy = (N + 127) / 128;

    // ---- layer 0: x (fp32) -> bufA (fp16) ----
    zero_att<<<blocks((long)N * 8, TB), TB>>>(el, gmax, N * 8);
    gemm_fp16<true, false, false><<<dim3(2, gy), 256>>>(x, nullptr, W0, hfeat,
                                                        N, 256, 256, al0, ar0, el, er);
    gmax_kernel<<<128, 256>>>(el, gmax, N * 4);
    gat_aggregate<64, 0><<<aggBlocks, 256>>>(rowptr, srcS, el, er, gmax, hfeat, b0, bufA, nullptr, N);

    // ---- layer 1: bufA (fp16) -> bufB (fp16) ----
    zero_att<<<blocks((long)N * 8, TB), TB>>>(el, gmax, N * 8);
    gemm_fp16<true, false, true><<<dim3(2, gy), 256>>>(nullptr, bufA, W1, hfeat,
                                                       N, 256, 256, al1, ar1, el, er);
    gmax_kernel<<<128, 256>>>(el, gmax, N * 4);
    gat_aggregate<64, 0><<<aggBlocks, 256>>>(rowptr, srcS, el, er, gmax, hfeat, b1, bufB, nullptr, N);

    // ---- layer 2: bufB (fp16) -> logits; el/er via appended GEMM columns ----
    build_w2ext<<<blocks(256 * 168, TB), TB>>>(W2, al2, ar2, W2e);
    gemm_fp16<false, true, true><<<dim3(2, gy), 256>>>(nullptr, bufB, W2e, hfeat,
                                                       N, 256, 168, nullptr, nullptr, el, er);
    zero_int<<<1, 32>>>((int*)gmax, 4);
    gmax_kernel<<<128, 256>>>(el, gmax, N * 4);
    gat_aggregate<40, 1><<<aggBlocks, 256>>>(rowptr, srcS, el, er, gmax, hfeat, b2, nullptr, (float*)d_out, N);
}